// round 1
// baseline (speedup 1.0000x reference)
#include <cuda_runtime.h>

// DiffeomorphicTransform: scaling-and-squaring integration of a stationary
// velocity field. velocity [32, 2, 768, 768] fp32 -> flow (same shape).
//
// flow = velocity / 2^7
// repeat 7x: flow = flow + bilinear_sample(flow, id + flow)   (zero padding)
//
// Fusion: the division by 2^7 is folded into the first step kernel as a
// per-load scale, eliminating a separate init pass (saves ~300 MB traffic).
// Ping-pong between d_out and a __device__ scratch buffer; 7 steps (odd)
// starting with dst=d_out means the final result lands in d_out.

constexpr int B  = 32;
constexpr int H  = 768;
constexpr int W  = 768;
constexpr int HW = H * W;
constexpr int NPIX = B * HW;          // 18,874,368 pixels

// Scratch ping-pong buffer (allocation-free: static __device__ global).
__device__ float g_scratch[(size_t)B * 2 * HW];

__global__ void __launch_bounds__(256)
diffeo_step_kernel(const float* __restrict__ src, float* __restrict__ dst,
                   float scale)
{
    int idx = blockIdx.x * blockDim.x + threadIdx.x;
    if (idx >= NPIX) return;

    int x   = idx % W;
    int rem = idx / W;
    int y   = rem % H;
    int b   = rem / H;

    const float* __restrict__ s0 = src + (size_t)b * 2 * HW;  // plane 0: dy
    const float* __restrict__ s1 = s0 + HW;                    // plane 1: dx

    int pix = y * W + x;
    float dy = __ldg(s0 + pix) * scale;
    float dx = __ldg(s1 + pix) * scale;

    float cy = (float)y + dy;
    float cx = (float)x + dx;

    float y0f = floorf(cy);
    float x0f = floorf(cx);
    float wy  = cy - y0f;
    float wx  = cx - x0f;

    int y0 = (int)y0f;
    int x0 = (int)x0f;
    int y1 = y0 + 1;
    int x1 = x0 + 1;

    // validity masks (zero padding: out-of-range corners contribute 0)
    float vy0 = (y0 >= 0 && y0 < H) ? 1.0f : 0.0f;
    float vy1 = (y1 >= 0 && y1 < H) ? 1.0f : 0.0f;
    float vx0 = (x0 >= 0 && x0 < W) ? 1.0f : 0.0f;
    float vx1 = (x1 >= 0 && x1 < W) ? 1.0f : 0.0f;

    int yc0 = min(max(y0, 0), H - 1);
    int yc1 = min(max(y1, 0), H - 1);
    int xc0 = min(max(x0, 0), W - 1);
    int xc1 = min(max(x1, 0), W - 1);

    float w00 = (1.0f - wy) * (1.0f - wx) * vy0 * vx0;
    float w01 = (1.0f - wy) * wx          * vy0 * vx1;
    float w10 = wy          * (1.0f - wx) * vy1 * vx0;
    float w11 = wy          * wx          * vy1 * vx1;

    int l00 = yc0 * W + xc0;
    int l01 = yc0 * W + xc1;
    int l10 = yc1 * W + xc0;
    int l11 = yc1 * W + xc1;

    // taps: same linear index for both channels, one address calc
    float a0 = w00 * __ldg(s0 + l00) + w01 * __ldg(s0 + l01)
             + w10 * __ldg(s0 + l10) + w11 * __ldg(s0 + l11);
    float a1 = w00 * __ldg(s1 + l00) + w01 * __ldg(s1 + l01)
             + w10 * __ldg(s1 + l10) + w11 * __ldg(s1 + l11);

    float* __restrict__ d0 = dst + (size_t)b * 2 * HW;
    d0[pix]      = dy + a0 * scale;
    d0[pix + HW] = dx + a1 * scale;
}

extern "C" void kernel_launch(void* const* d_in, const int* in_sizes, int n_in,
                              void* d_out, int out_size)
{
    const float* velocity = (const float*)d_in[0];
    float* out = (float*)d_out;

    float* scratch = nullptr;
    cudaGetSymbolAddress((void**)&scratch, g_scratch);

    const int threads = 256;
    const int blocks  = (NPIX + threads - 1) / threads;
    const float inv128 = 1.0f / 128.0f;   // 2^-TIME_STEP, TIME_STEP = 7

    // 7 squaring steps; first step folds the /128 scale on every src read.
    diffeo_step_kernel<<<blocks, threads>>>(velocity, out, inv128);  // 1
    diffeo_step_kernel<<<blocks, threads>>>(out, scratch, 1.0f);     // 2
    diffeo_step_kernel<<<blocks, threads>>>(scratch, out, 1.0f);     // 3
    diffeo_step_kernel<<<blocks, threads>>>(out, scratch, 1.0f);     // 4
    diffeo_step_kernel<<<blocks, threads>>>(scratch, out, 1.0f);     // 5
    diffeo_step_kernel<<<blocks, threads>>>(out, scratch, 1.0f);     // 6
    diffeo_step_kernel<<<blocks, threads>>>(scratch, out, 1.0f);     // 7
}

// round 2
// speedup vs baseline: 1.0378x; 1.0378x over previous
#include <cuda_runtime.h>

// DiffeomorphicTransform: scaling-and-squaring integration.
// velocity [32, 2, 768, 768] fp32 -> flow (same shape).
// flow = velocity / 2^7; repeat 7x: flow += bilinear(flow, id + flow), zero pad.
//
// R2: float4 vectorization (4 px/thread) + interior fast path (no clamps/masks
// for the >97% of pixels whose 4 taps are fully in-bounds).

constexpr int B  = 32;
constexpr int H  = 768;
constexpr int W  = 768;
constexpr int HW = H * W;
constexpr int NPIX  = B * HW;
constexpr int NVEC  = NPIX / 4;      // 4 pixels per thread

__device__ float g_scratch[(size_t)B * 2 * HW];

__global__ void __launch_bounds__(256)
diffeo_step_kernel(const float* __restrict__ src, float* __restrict__ dst,
                   float scale)
{
    int t = blockIdx.x * blockDim.x + threadIdx.x;
    if (t >= NVEC) return;

    int idx = t * 4;                  // first pixel of this thread's group
    int x   = idx % W;                // W % 4 == 0: group never crosses a row
    int rem = idx / W;
    int y   = rem % H;
    int b   = rem / H;

    const float* __restrict__ s0 = src + (size_t)b * 2 * HW;  // ch0: dy
    const float* __restrict__ s1 = s0 + HW;                   // ch1: dx

    int pix = y * W + x;
    float4 vy4 = __ldg((const float4*)(s0 + pix));
    float4 vx4 = __ldg((const float4*)(s1 + pix));

    float dy[4] = {vy4.x * scale, vy4.y * scale, vy4.z * scale, vy4.w * scale};
    float dx[4] = {vx4.x * scale, vx4.y * scale, vx4.z * scale, vx4.w * scale};

    float o0[4], o1[4];
    float fy = (float)y;

    #pragma unroll
    for (int i = 0; i < 4; i++) {
        float cy = fy + dy[i];
        float cx = (float)(x + i) + dx[i];

        int   y0 = __float2int_rd(cy);
        int   x0 = __float2int_rd(cx);
        float wy = cy - (float)y0;
        float wx = cx - (float)x0;

        float a0, a1;
        if ((unsigned)y0 < (unsigned)(H - 1) && (unsigned)x0 < (unsigned)(W - 1)) {
            // Fast path: all 4 taps in-bounds, contiguous addressing.
            int l = y0 * W + x0;
            float w11 = wy * wx;
            float w10 = wy - w11;            // wy*(1-wx)
            float w01 = wx - w11;            // (1-wy)*wx
            float w00 = 1.0f - wy - w01;     // (1-wy)*(1-wx)
            a0 = w00 * __ldg(s0 + l)     + w01 * __ldg(s0 + l + 1)
               + w10 * __ldg(s0 + l + W) + w11 * __ldg(s0 + l + W + 1);
            a1 = w00 * __ldg(s1 + l)     + w01 * __ldg(s1 + l + 1)
               + w10 * __ldg(s1 + l + W) + w11 * __ldg(s1 + l + W + 1);
        } else {
            // Border path: per-corner zero padding, clamped indices.
            int y1 = y0 + 1, x1 = x0 + 1;
            float vy0 = ((unsigned)y0 < (unsigned)H) ? 1.0f : 0.0f;
            float vy1 = ((unsigned)y1 < (unsigned)H) ? 1.0f : 0.0f;
            float vx0 = ((unsigned)x0 < (unsigned)W) ? 1.0f : 0.0f;
            float vx1 = ((unsigned)x1 < (unsigned)W) ? 1.0f : 0.0f;
            int yc0 = min(max(y0, 0), H - 1);
            int yc1 = min(max(y1, 0), H - 1);
            int xc0 = min(max(x0, 0), W - 1);
            int xc1 = min(max(x1, 0), W - 1);
            float w00 = (1.0f - wy) * (1.0f - wx) * vy0 * vx0;
            float w01 = (1.0f - wy) * wx          * vy0 * vx1;
            float w10 = wy          * (1.0f - wx) * vy1 * vx0;
            float w11 = wy          * wx          * vy1 * vx1;
            int l00 = yc0 * W + xc0, l01 = yc0 * W + xc1;
            int l10 = yc1 * W + xc0, l11 = yc1 * W + xc1;
            a0 = w00 * __ldg(s0 + l00) + w01 * __ldg(s0 + l01)
               + w10 * __ldg(s0 + l10) + w11 * __ldg(s0 + l11);
            a1 = w00 * __ldg(s1 + l00) + w01 * __ldg(s1 + l01)
               + w10 * __ldg(s1 + l10) + w11 * __ldg(s1 + l11);
        }
        o0[i] = dy[i] + a0 * scale;
        o1[i] = dx[i] + a1 * scale;
    }

    float* __restrict__ d0 = dst + (size_t)b * 2 * HW;
    *(float4*)(d0 + pix)      = make_float4(o0[0], o0[1], o0[2], o0[3]);
    *(float4*)(d0 + pix + HW) = make_float4(o1[0], o1[1], o1[2], o1[3]);
}

extern "C" void kernel_launch(void* const* d_in, const int* in_sizes, int n_in,
                              void* d_out, int out_size)
{
    const float* velocity = (const float*)d_in[0];
    float* out = (float*)d_out;

    float* scratch = nullptr;
    cudaGetSymbolAddress((void**)&scratch, g_scratch);

    const int threads = 256;
    const int blocks  = (NVEC + threads - 1) / threads;
    const float inv128 = 1.0f / 128.0f;   // 2^-TIME_STEP, TIME_STEP = 7

    diffeo_step_kernel<<<blocks, threads>>>(velocity, out, inv128);  // 1
    diffeo_step_kernel<<<blocks, threads>>>(out, scratch, 1.0f);     // 2
    diffeo_step_kernel<<<blocks, threads>>>(scratch, out, 1.0f);     // 3
    diffeo_step_kernel<<<blocks, threads>>>(out, scratch, 1.0f);     // 4
    diffeo_step_kernel<<<blocks, threads>>>(scratch, out, 1.0f);     // 5
    diffeo_step_kernel<<<blocks, threads>>>(out, scratch, 1.0f);     // 6
    diffeo_step_kernel<<<blocks, threads>>>(scratch, out, 1.0f);     // 7
}

// round 3
// speedup vs baseline: 1.1202x; 1.0794x over previous
#include <cuda_runtime.h>

// DiffeomorphicTransform: scaling-and-squaring integration.
// velocity [32, 2, 768, 768] fp32 -> flow (same shape, planar).
//
// R3: channel-interleaved intermediate layout [B, H, W, 2]. Each bilinear tap
// fetches both channels with ONE aligned float2 load (8 gather LDGs -> 4),
// and 1 pixel/thread keeps gather lanes unit-stride (minimum L1 wavefronts).
// Step 1: planar velocity (scale folded) -> interleaved A.
// Steps 2-6: interleaved ping-pong A<->B.
// Step 7: interleaved -> planar d_out.

constexpr int B  = 32;
constexpr int H  = 768;
constexpr int W  = 768;
constexpr int HW = H * W;
constexpr int NPIX = B * HW;   // 18,874,368

// Ping-pong scratch (interleaved float2 per pixel). Static: allocation-free.
__device__ float2 g_bufA[(size_t)B * HW];
__device__ float2 g_bufB[(size_t)B * HW];

// ---------------------------------------------------------------------------
// Gather helpers
// ---------------------------------------------------------------------------

// One zero-padded tap from an interleaved field (both channels at once).
__device__ __forceinline__ float2 tap_border(const float2* __restrict__ base,
                                             int yy, int xx)
{
    bool valid = ((unsigned)yy < (unsigned)H) && ((unsigned)xx < (unsigned)W);
    int yc = min(max(yy, 0), H - 1);
    int xc = min(max(xx, 0), W - 1);
    float2 v = __ldg(base + yc * W + xc);
    float m = valid ? 1.0f : 0.0f;
    return make_float2(v.x * m, v.y * m);
}

// ---------------------------------------------------------------------------
// IN_PLANAR: src is [2, H, W] planar per batch (used only for step 1).
// OUT_PLANAR: dst is [2, H, W] planar per batch (used only for step 7).
// ---------------------------------------------------------------------------
template<bool IN_PLANAR, bool OUT_PLANAR>
__global__ void __launch_bounds__(256)
diffeo_step(const float* __restrict__ src, float* __restrict__ dst, float scale)
{
    int idx = blockIdx.x * blockDim.x + threadIdx.x;
    if (idx >= NPIX) return;

    int x   = idx % W;
    int rem = idx / W;
    int y   = rem % H;
    int b   = rem / H;
    int pix = y * W + x;

    // --- own-pixel displacement ---
    float dy, dx;
    const float* s0 = nullptr;                 // planar channel bases (step 1)
    const float* s1 = nullptr;
    const float2* si = nullptr;                // interleaved base (steps 2+)
    if (IN_PLANAR) {
        s0 = src + (size_t)b * 2 * HW;
        s1 = s0 + HW;
        dy = __ldg(s0 + pix) * scale;
        dx = __ldg(s1 + pix) * scale;
    } else {
        si = (const float2*)src + (size_t)b * HW;
        float2 v = __ldg(si + pix);
        dy = v.x * scale;
        dx = v.y * scale;
    }

    float cy = (float)y + dy;
    float cx = (float)x + dx;

    int   y0 = __float2int_rd(cy);
    int   x0 = __float2int_rd(cx);
    float wy = cy - (float)y0;
    float wx = cx - (float)x0;

    float a0, a1;
    if ((unsigned)y0 < (unsigned)(H - 1) && (unsigned)x0 < (unsigned)(W - 1)) {
        // Interior fast path: all 4 taps in-bounds.
        float w11 = wy * wx;
        float w10 = wy - w11;            // wy*(1-wx)
        float w01 = wx - w11;            // (1-wy)*wx
        float w00 = 1.0f - wy - w01;     // (1-wy)*(1-wx)
        int l = y0 * W + x0;
        if (IN_PLANAR) {
            a0 = w00 * __ldg(s0 + l)     + w01 * __ldg(s0 + l + 1)
               + w10 * __ldg(s0 + l + W) + w11 * __ldg(s0 + l + W + 1);
            a1 = w00 * __ldg(s1 + l)     + w01 * __ldg(s1 + l + 1)
               + w10 * __ldg(s1 + l + W) + w11 * __ldg(s1 + l + W + 1);
        } else {
            float2 t00 = __ldg(si + l);
            float2 t01 = __ldg(si + l + 1);
            float2 t10 = __ldg(si + l + W);
            float2 t11 = __ldg(si + l + W + 1);
            a0 = w00 * t00.x + w01 * t01.x + w10 * t10.x + w11 * t11.x;
            a1 = w00 * t00.y + w01 * t01.y + w10 * t10.y + w11 * t11.y;
        }
    } else {
        // Border path: per-corner zero padding.
        int y1 = y0 + 1, x1 = x0 + 1;
        float w11 = wy * wx;
        float w10 = wy - w11;
        float w01 = wx - w11;
        float w00 = 1.0f - wy - w01;
        if (IN_PLANAR) {
            float vy0 = ((unsigned)y0 < (unsigned)H) ? 1.0f : 0.0f;
            float vy1 = ((unsigned)y1 < (unsigned)H) ? 1.0f : 0.0f;
            float vx0 = ((unsigned)x0 < (unsigned)W) ? 1.0f : 0.0f;
            float vx1 = ((unsigned)x1 < (unsigned)W) ? 1.0f : 0.0f;
            int yc0 = min(max(y0, 0), H - 1);
            int yc1 = min(max(y1, 0), H - 1);
            int xc0 = min(max(x0, 0), W - 1);
            int xc1 = min(max(x1, 0), W - 1);
            float m00 = w00 * vy0 * vx0, m01 = w01 * vy0 * vx1;
            float m10 = w10 * vy1 * vx0, m11 = w11 * vy1 * vx1;
            int l00 = yc0 * W + xc0, l01 = yc0 * W + xc1;
            int l10 = yc1 * W + xc0, l11 = yc1 * W + xc1;
            a0 = m00 * __ldg(s0 + l00) + m01 * __ldg(s0 + l01)
               + m10 * __ldg(s0 + l10) + m11 * __ldg(s0 + l11);
            a1 = m00 * __ldg(s1 + l00) + m01 * __ldg(s1 + l01)
               + m10 * __ldg(s1 + l10) + m11 * __ldg(s1 + l11);
        } else {
            float2 t00 = tap_border(si, y0, x0);
            float2 t01 = tap_border(si, y0, x1);
            float2 t10 = tap_border(si, y1, x0);
            float2 t11 = tap_border(si, y1, x1);
            a0 = w00 * t00.x + w01 * t01.x + w10 * t10.x + w11 * t11.x;
            a1 = w00 * t00.y + w01 * t01.y + w10 * t10.y + w11 * t11.y;
        }
    }

    float o0 = dy + a0 * scale;
    float o1 = dx + a1 * scale;

    if (OUT_PLANAR) {
        float* d0 = dst + (size_t)b * 2 * HW;
        d0[pix]      = o0;
        d0[pix + HW] = o1;
    } else {
        float2* di = (float2*)dst + (size_t)b * HW;
        di[pix] = make_float2(o0, o1);
    }
}

extern "C" void kernel_launch(void* const* d_in, const int* in_sizes, int n_in,
                              void* d_out, int out_size)
{
    const float* velocity = (const float*)d_in[0];
    float* out = (float*)d_out;

    float *bufA = nullptr, *bufB = nullptr;
    cudaGetSymbolAddress((void**)&bufA, g_bufA);
    cudaGetSymbolAddress((void**)&bufB, g_bufB);

    const int threads = 256;
    const int blocks  = (NPIX + threads - 1) / threads;
    const float inv128 = 1.0f / 128.0f;   // 2^-TIME_STEP, TIME_STEP = 7

    // step 1: planar velocity (scaled) -> interleaved A
    diffeo_step<true,  false><<<blocks, threads>>>(velocity, bufA, inv128);
    // steps 2-6: interleaved ping-pong
    diffeo_step<false, false><<<blocks, threads>>>(bufA, bufB, 1.0f);
    diffeo_step<false, false><<<blocks, threads>>>(bufB, bufA, 1.0f);
    diffeo_step<false, false><<<blocks, threads>>>(bufA, bufB, 1.0f);
    diffeo_step<false, false><<<blocks, threads>>>(bufB, bufA, 1.0f);
    diffeo_step<false, false><<<blocks, threads>>>(bufA, bufB, 1.0f);
    // step 7: interleaved -> planar d_out
    diffeo_step<false, true ><<<blocks, threads>>>(bufB, out, 1.0f);
}